// round 3
// baseline (speedup 1.0000x reference)
#include <cuda_runtime.h>

#define BB 64      // batch
#define SS 512     // sequence length
#define EE 256     // embedding dim
#define HH 512     // hidden
#define GG 2048    // 4*H gate rows

typedef unsigned long long u64;
typedef unsigned int u32;

// ---------------------------------------------------------------------------
// Device globals
// ---------------------------------------------------------------------------
__device__ int g_is64;
__device__ unsigned g_bar;                    // monotonic grid-barrier counter
__device__ float g_xg[SS * GG * BB];          // x_gates [s][g][b]
__device__ float g_h[2][HH * BB];             // double-buffered h [k][b]

// ---------------------------------------------------------------------------
// f32x2 helpers (packed FFMA2 -- only reachable via PTX)
// ---------------------------------------------------------------------------
__device__ __forceinline__ u64 fma2(u64 a, u64 b, u64 c) {
    u64 d; asm("fma.rn.f32x2 %0, %1, %2, %3;" : "=l"(d) : "l"(a), "l"(b), "l"(c)); return d;
}
__device__ __forceinline__ u64 pack2(float x, float y) {
    u64 d; asm("mov.b64 %0, {%1, %2};" : "=l"(d) : "f"(x), "f"(y)); return d;
}
__device__ __forceinline__ float2 unpack2(u64 v) {
    float2 r; asm("mov.b64 {%0, %1}, %2;" : "=f"(r.x), "=f"(r.y) : "l"(v)); return r;
}
__device__ __forceinline__ float sigf(float x) { return 1.f / (1.f + __expf(-x)); }
__device__ __forceinline__ float tanh_f(float x) { return 2.f / (1.f + __expf(-2.f * x)) - 1.f; }

// ---------------------------------------------------------------------------
// dtype detection
// ---------------------------------------------------------------------------
__global__ void detect_dtype(const void* seq) {
    if (threadIdx.x == 0 && blockIdx.x == 0) {
        const unsigned* p = (const unsigned*)seq;
        int is64 = 1;
        for (int i = 0; i < 64; i++) {
            if (p[2 * i + 1] != 0u) { is64 = 0; break; }
        }
        g_is64 = is64;
    }
}

// ---------------------------------------------------------------------------
// Phase A: x_gates[s][g][b] = emb[seq[b][s]] . W_ih[g] + b_ih[g] + b_hh[g]
// Tile: 128 M (2 s-values x 64 b) x 64 N, BK=16. Thread: 8 M x 4 N via f32x2
// (vector = M-pair). 16 FFMA2 : 4 LDS.128 per kk -> FMA-bound.
// ---------------------------------------------------------------------------
__global__ void __launch_bounds__(256) xgates_gemm(
    const void* __restrict__ seq,
    const float* __restrict__ emb,
    const float* __restrict__ Wih,
    const float* __restrict__ bih,
    const float* __restrict__ bhh)
{
    __shared__ float  As[16][132];   // [k][m]  (row 528B, 16B-aligned)
    __shared__ float2 Bs2[16][66];   // [k][j_local] duplicated {w,w}
    __shared__ int rows[128];

    const int tid = threadIdx.x;
    const int s0 = blockIdx.y * 2;
    const int g0 = blockIdx.x * 64;

    if (tid < 128) {
        int b = tid & 63, sl = tid >> 6;
        int idx;
        if (g_is64) idx = (int)((const long long*)seq)[b * SS + s0 + sl];
        else        idx = ((const int*)seq)[b * SS + s0 + sl];
        rows[tid] = idx;
    }
    __syncthreads();

    const int tx = tid & 15;          // M dir: 8 m each
    const int ty = tid >> 4;          // N dir: 4 j each
    const int arow = tid >> 1;        // As loader: m row
    const int ak   = (tid & 1) * 8;   // k offset (8 floats)
    const int wrow = tid >> 2;        // Bs loader: j row
    const int wk   = (tid & 3) * 4;   // k offset (4 floats)

    u64 cc[4][4];
    #pragma unroll
    for (int mp = 0; mp < 4; mp++)
        #pragma unroll
        for (int jn = 0; jn < 4; jn++) cc[mp][jn] = 0ull;

    for (int k0 = 0; k0 < EE; k0 += 16) {
        const float* ap = emb + (size_t)rows[arow] * EE + k0 + ak;
        float4 a0 = *(const float4*)ap;
        float4 a1 = *(const float4*)(ap + 4);
        As[ak + 0][arow] = a0.x; As[ak + 1][arow] = a0.y;
        As[ak + 2][arow] = a0.z; As[ak + 3][arow] = a0.w;
        As[ak + 4][arow] = a1.x; As[ak + 5][arow] = a1.y;
        As[ak + 6][arow] = a1.z; As[ak + 7][arow] = a1.w;
        float4 wv = *(const float4*)&Wih[(size_t)(g0 + wrow) * EE + k0 + wk];
        Bs2[wk + 0][wrow] = make_float2(wv.x, wv.x);
        Bs2[wk + 1][wrow] = make_float2(wv.y, wv.y);
        Bs2[wk + 2][wrow] = make_float2(wv.z, wv.z);
        Bs2[wk + 3][wrow] = make_float2(wv.w, wv.w);
        __syncthreads();

        #pragma unroll
        for (int kk = 0; kk < 16; kk++) {
            u64 a0p = *(const u64*)&As[kk][tx * 8 + 0];
            u64 a1p = *(const u64*)&As[kk][tx * 8 + 2];
            u64 a2p = *(const u64*)&As[kk][tx * 8 + 4];
            u64 a3p = *(const u64*)&As[kk][tx * 8 + 6];
            u64 w0 = *(const u64*)&Bs2[kk][ty * 4 + 0];
            u64 w1 = *(const u64*)&Bs2[kk][ty * 4 + 1];
            u64 w2 = *(const u64*)&Bs2[kk][ty * 4 + 2];
            u64 w3 = *(const u64*)&Bs2[kk][ty * 4 + 3];
            cc[0][0] = fma2(a0p, w0, cc[0][0]); cc[1][0] = fma2(a1p, w0, cc[1][0]);
            cc[2][0] = fma2(a2p, w0, cc[2][0]); cc[3][0] = fma2(a3p, w0, cc[3][0]);
            cc[0][1] = fma2(a0p, w1, cc[0][1]); cc[1][1] = fma2(a1p, w1, cc[1][1]);
            cc[2][1] = fma2(a2p, w1, cc[2][1]); cc[3][1] = fma2(a3p, w1, cc[3][1]);
            cc[0][2] = fma2(a0p, w2, cc[0][2]); cc[1][2] = fma2(a1p, w2, cc[1][2]);
            cc[2][2] = fma2(a2p, w2, cc[2][2]); cc[3][2] = fma2(a3p, w2, cc[3][2]);
            cc[0][3] = fma2(a0p, w3, cc[0][3]); cc[1][3] = fma2(a1p, w3, cc[1][3]);
            cc[2][3] = fma2(a2p, w3, cc[2][3]); cc[3][3] = fma2(a3p, w3, cc[3][3]);
        }
        __syncthreads();
    }

    // epilogue: thread's 8 m are within one s: s = s0 + (tx>>3), b0 = (tx&7)*8
    const int s  = s0 + (tx >> 3);
    const int b0 = (tx & 7) * 8;
    #pragma unroll
    for (int jn = 0; jn < 4; jn++) {
        int g = g0 + ty * 4 + jn;
        float bsum = bih[g] + bhh[g];
        float2 p0 = unpack2(cc[0][jn]);
        float2 p1 = unpack2(cc[1][jn]);
        float2 p2 = unpack2(cc[2][jn]);
        float2 p3 = unpack2(cc[3][jn]);
        float* dst = &g_xg[(size_t)s * (GG * BB) + (size_t)g * BB + b0];
        *(float4*)dst       = make_float4(p0.x + bsum, p0.y + bsum, p1.x + bsum, p1.y + bsum);
        *(float4*)(dst + 4) = make_float4(p2.x + bsum, p2.y + bsum, p3.x + bsum, p3.y + bsum);
    }
}

// ---------------------------------------------------------------------------
// Release/acquire grid barrier (monotonic; graph-replay safe). grid = 128.
// ---------------------------------------------------------------------------
__device__ __forceinline__ void grid_sync128() {
    __syncthreads();
    if (threadIdx.x == 0) {
        unsigned t;
        asm volatile("atom.release.gpu.global.add.u32 %0, [%1], 1;"
                     : "=r"(t) : "l"(&g_bar) : "memory");
        unsigned target = (t / 128u + 1u) * 128u;
        unsigned cur;
        do {
            asm volatile("ld.acquire.gpu.global.u32 %0, [%1];"
                         : "=r"(cur) : "l"(&g_bar) : "memory");
        } while (cur < target);
    }
    __syncthreads();
}

// ---------------------------------------------------------------------------
// Phase B: persistent LSTM recurrence. 128 CTAs x 256 threads (8 warps).
// CTA owns 4 h-columns j0..j0+3 (16 gate rows). Warp wi: k-range kr=wi>>1
// (128 k) x b-half bh=wi&1 (32 b). Each (k,b) staged once per CTA via
// double-buffered cp.async.cg. f32x2 accumulators (vector = j-pair).
// SMEM: W pairs 32KB | h 128KB | scratch 16KB = 176KB.
// ---------------------------------------------------------------------------
__global__ void __launch_bounds__(256, 1) lstm_kernel(
    const float* __restrict__ Whh, float* __restrict__ out, int write_c)
{
    extern __shared__ float smf[];
    float*  Ws  = smf;                       // (st*512+k)*2 : {w_jA, w_jB}
    float*  hsf = smf + 8192;                // hs[k*64 + b]  (128KB)
    float2* scp = (float2*)(smf + 40960);    // [st8][bh2][kr4][lane32] float2

    const int tid  = threadIdx.x;
    const int wi   = tid >> 5;
    const int lane = tid & 31;
    const int kr   = wi >> 1;     // k-range index (0..3): 128 k
    const int bh   = wi & 1;      // b-half (0..1): 32 b
    const int j0   = blockIdx.x * 4;

    u32 sbase;
    asm("{ .reg .u64 t; cvta.to.shared.u64 t, %1; cvt.u32.u64 %0, t; }"
        : "=r"(sbase) : "l"(smf));
    const u32 hs_u32 = sbase + 8192u * 4u;

    // W pairs: st = g*2+jp covers rows (g*H + j0+2jp, +1)
    #pragma unroll
    for (int st = 0; st < 8; st++) {
        int g = st >> 1, jp = st & 1;
        const float* r0 = Whh + (size_t)(g * HH + j0 + 2 * jp) * HH;
        const float* r1 = r0 + HH;
        #pragma unroll
        for (int i = 0; i < 2; i++) {
            int k = tid + i * 256;
            *(float2*)&Ws[(st * 512 + k) * 2] = make_float2(r0[k], r1[k]);
        }
    }

    // zero h read-buffer for step 0 (our 4 columns)
    g_h[1][(j0 + (tid >> 6)) * 64 + (tid & 63)] = 0.f;

    const int b  = tid & 63;        // epilogue mapping: one (b, j) per thread
    const int jj = tid >> 6;        // 0..3
    const int j  = j0 + jj;
    const int jp_r  = jj >> 1;      // which stream pair
    const int comp  = jj & 1;       // x or y of f32x2
    const int bh_r  = b >> 5;
    const int lane_r = b & 31;

    float c_reg = 0.f, h_val = 0.f;

    #pragma unroll 1
    for (int s = 0; s < SS; s++) {
        grid_sync128();

        // prefetch xg operands (DRAM latency hides under the GEMM)
        float xgv[4];
        const float* xgs = g_xg + (size_t)s * (GG * BB);
        #pragma unroll
        for (int g = 0; g < 4; g++)
            xgv[g] = __ldg(&xgs[(g * HH + j) * BB + b]);

        const char* hsrc = (const char*)g_h[(s + 1) & 1];

        u64 acc[8];
        #pragma unroll
        for (int st = 0; st < 8; st++) acc[st] = 0ull;

        // stage chunk 0: 32 k-rows x 32 b-half (4KB per warp-chunk)
        {
            #pragma unroll
            for (int i = 0; i < 8; i++) {
                int idx = lane + i * 32;                 // 0..255
                u32 off = (u32)(((kr * 128 + (idx >> 3)) * 64 + bh * 32) * 4
                                + (idx & 7) * 16);
                asm volatile("cp.async.cg.shared.global [%0], [%1], 16;"
                             :: "r"(hs_u32 + off), "l"(hsrc + off));
            }
            asm volatile("cp.async.commit_group;" ::: "memory");
        }

        #pragma unroll
        for (int c = 0; c < 4; c++) {
            if (c < 3) {
                #pragma unroll
                for (int i = 0; i < 8; i++) {
                    int idx = lane + i * 32;
                    u32 off = (u32)(((kr * 128 + (c + 1) * 32 + (idx >> 3)) * 64
                                     + bh * 32) * 4 + (idx & 7) * 16);
                    asm volatile("cp.async.cg.shared.global [%0], [%1], 16;"
                                 :: "r"(hs_u32 + off), "l"(hsrc + off));
                }
                asm volatile("cp.async.commit_group;" ::: "memory");
                asm volatile("cp.async.wait_group 1;" ::: "memory");
            } else {
                asm volatile("cp.async.wait_group 0;" ::: "memory");
            }
            __syncwarp();

            const int kbase = kr * 128 + c * 32;
            #pragma unroll
            for (int k2 = 0; k2 < 16; k2++) {
                const int k = kbase + k2 * 2;
                float h0 = hsf[k * 64 + bh * 32 + lane];
                float h1 = hsf[(k + 1) * 64 + bh * 32 + lane];
                u64 d0 = pack2(h0, h0);
                u64 d1 = pack2(h1, h1);
                #pragma unroll
                for (int st = 0; st < 8; st++) {
                    ulonglong2 wv = *(const ulonglong2*)&Ws[(st * 512 + k) * 2];
                    acc[st] = fma2(d0, wv.x, acc[st]);
                    acc[st] = fma2(d1, wv.y, acc[st]);
                }
            }
        }

        // partials -> scratch: [st][bh][kr][lane], lanes contiguous
        #pragma unroll
        for (int st = 0; st < 8; st++)
            scp[((st * 2 + bh) * 4 + kr) * 32 + lane] = *(float2*)&acc[st];
        __syncthreads();

        // cross-warp reduce (4 k-range partials) + gates
        float gt[4];
        #pragma unroll
        for (int g = 0; g < 4; g++) {
            int st = g * 2 + jp_r;
            const float2* base = &scp[((st * 2 + bh_r) * 4) * 32 + lane_r];
            float2 p0 = base[0 * 32];
            float2 p1 = base[1 * 32];
            float2 p2 = base[2 * 32];
            float2 p3 = base[3 * 32];
            float sx = p0.x + p1.x + p2.x + p3.x;
            float sy = p0.y + p1.y + p2.y + p3.y;
            gt[g] = (comp ? sy : sx) + xgv[g];
        }
        float ig = sigf(gt[0]), fg = sigf(gt[1]);
        float gg = tanh_f(gt[2]), og = sigf(gt[3]);
        c_reg = fg * c_reg + ig * gg;
        h_val = og * tanh_f(c_reg);

        g_h[s & 1][j * 64 + b] = h_val;
    }

    out[b * HH + j] = h_val;
    if (write_c) out[BB * HH + b * HH + j] = c_reg;
}

// ---------------------------------------------------------------------------
// kernel_launch
// ---------------------------------------------------------------------------
extern "C" void kernel_launch(void* const* d_in, const int* in_sizes, int n_in,
                              void* d_out, int out_size)
{
    const void*  seq = d_in[0];
    const float* emb = (const float*)d_in[1];
    const float* Wih = (const float*)d_in[2];
    const float* Whh = (const float*)d_in[3];
    const float* bih = (const float*)d_in[4];
    const float* bhh = (const float*)d_in[5];
    float* out = (float*)d_out;

    (void)in_sizes; (void)n_in;
    int write_c = (out_size >= 2 * BB * HH) ? 1 : 0;

    // 176 KB dynamic SMEM: W pairs 32K + h 128K + scratch 16K
    static const int kSmem = (8192 + 32768 + 4096) * (int)sizeof(float);
    cudaFuncSetAttribute(lstm_kernel, cudaFuncAttributeMaxDynamicSharedMemorySize, kSmem);

    detect_dtype<<<1, 32>>>(seq);
    xgates_gemm<<<dim3(GG / 64, SS / 2), 256>>>(seq, emb, Wih, bih, bhh);
    lstm_kernel<<<HH / 4, 256, kSmem>>>(Whh, out, write_c);
}

// round 4
// speedup vs baseline: 1.3070x; 1.3070x over previous
#include <cuda_runtime.h>

#define BB 64      // batch
#define SS 512     // sequence length
#define EE 256     // embedding dim
#define HH 512     // hidden
#define GG 2048    // 4*H gate rows

typedef unsigned long long u64;
typedef unsigned int u32;

// ---------------------------------------------------------------------------
// Device globals
// ---------------------------------------------------------------------------
__device__ unsigned g_bar;                    // monotonic grid-barrier counter
__device__ float g_xg[SS * GG * BB];          // x_gates [s][g][b]
__device__ float g_h[2][HH * BB];             // double-buffered h [k][b]

// ---------------------------------------------------------------------------
// f32x2 helpers (packed FFMA2 -- only reachable via PTX)
// ---------------------------------------------------------------------------
__device__ __forceinline__ u64 fma2(u64 a, u64 b, u64 c) {
    u64 d; asm("fma.rn.f32x2 %0, %1, %2, %3;" : "=l"(d) : "l"(a), "l"(b), "l"(c)); return d;
}
__device__ __forceinline__ u64 pack2(float x, float y) {
    u64 d; asm("mov.b64 %0, {%1, %2};" : "=l"(d) : "f"(x), "f"(y)); return d;
}
__device__ __forceinline__ float2 unpack2(u64 v) {
    float2 r; asm("mov.b64 {%0, %1}, %2;" : "=f"(r.x), "=f"(r.y) : "l"(v)); return r;
}
__device__ __forceinline__ float sigf(float x) { return 1.f / (1.f + __expf(-x)); }
__device__ __forceinline__ float tanh_f(float x) { return 2.f / (1.f + __expf(-2.f * x)) - 1.f; }

// ---------------------------------------------------------------------------
// Phase A: x_gates[s][g][b] = emb[seq[b][s]] . W_ih[g] + b_ih[g] + b_hh[g]
// Tile: 128 M (2 s x 64 b) x 64 N, BK=16. Thread: 8 M x 4 N via f32x2.
// M micro-mapping m = p*32 + tx*2 (+0,1): conflict-free LDS.64 A reads.
// Dtype detection (int32 vs int64 seq) done per-block in SMEM.
// ---------------------------------------------------------------------------
__global__ void __launch_bounds__(256) xgates_gemm(
    const void* __restrict__ seq,
    const float* __restrict__ emb,
    const float* __restrict__ Wih,
    const float* __restrict__ bih,
    const float* __restrict__ bhh)
{
    __shared__ float  As[16][132];   // [k][m]
    __shared__ float2 Bs2[16][66];   // [k][j_local] duplicated {w,w}
    __shared__ int rows[128];
    __shared__ int s_is64;

    const int tid = threadIdx.x;
    const int s0 = blockIdx.y * 2;
    const int g0 = blockIdx.x * 64;

    if (tid == 0) s_is64 = 1;
    __syncthreads();
    if (tid < 64) {
        if (((const u32*)seq)[2 * tid + 1] != 0u) s_is64 = 0;
    }
    __syncthreads();
    if (tid < 128) {
        int b = tid & 63, sl = tid >> 6;
        int idx;
        if (s_is64) idx = (int)((const long long*)seq)[b * SS + s0 + sl];
        else        idx = ((const int*)seq)[b * SS + s0 + sl];
        rows[tid] = idx;
    }
    __syncthreads();

    const int tx = tid & 15;          // M dir
    const int ty = tid >> 4;          // N dir: 4 j each
    const int arow = tid >> 1;        // As loader: m row
    const int ak   = (tid & 1) * 8;   // k offset (8 floats)
    const int wrow = tid >> 2;        // Bs loader: j row
    const int wk   = (tid & 3) * 4;   // k offset (4 floats)

    u64 cc[4][4];
    #pragma unroll
    for (int p = 0; p < 4; p++)
        #pragma unroll
        for (int jn = 0; jn < 4; jn++) cc[p][jn] = 0ull;

    for (int k0 = 0; k0 < EE; k0 += 16) {
        const float* ap = emb + (size_t)rows[arow] * EE + k0 + ak;
        float4 a0 = *(const float4*)ap;
        float4 a1 = *(const float4*)(ap + 4);
        As[ak + 0][arow] = a0.x; As[ak + 1][arow] = a0.y;
        As[ak + 2][arow] = a0.z; As[ak + 3][arow] = a0.w;
        As[ak + 4][arow] = a1.x; As[ak + 5][arow] = a1.y;
        As[ak + 6][arow] = a1.z; As[ak + 7][arow] = a1.w;
        float4 wv = *(const float4*)&Wih[(size_t)(g0 + wrow) * EE + k0 + wk];
        Bs2[wk + 0][wrow] = make_float2(wv.x, wv.x);
        Bs2[wk + 1][wrow] = make_float2(wv.y, wv.y);
        Bs2[wk + 2][wrow] = make_float2(wv.z, wv.z);
        Bs2[wk + 3][wrow] = make_float2(wv.w, wv.w);
        __syncthreads();

        #pragma unroll
        for (int kk = 0; kk < 16; kk++) {
            u64 a0p = *(const u64*)&As[kk][0 * 32 + tx * 2];
            u64 a1p = *(const u64*)&As[kk][1 * 32 + tx * 2];
            u64 a2p = *(const u64*)&As[kk][2 * 32 + tx * 2];
            u64 a3p = *(const u64*)&As[kk][3 * 32 + tx * 2];
            u64 w0 = *(const u64*)&Bs2[kk][ty * 4 + 0];
            u64 w1 = *(const u64*)&Bs2[kk][ty * 4 + 1];
            u64 w2 = *(const u64*)&Bs2[kk][ty * 4 + 2];
            u64 w3 = *(const u64*)&Bs2[kk][ty * 4 + 3];
            cc[0][0] = fma2(a0p, w0, cc[0][0]); cc[1][0] = fma2(a1p, w0, cc[1][0]);
            cc[2][0] = fma2(a2p, w0, cc[2][0]); cc[3][0] = fma2(a3p, w0, cc[3][0]);
            cc[0][1] = fma2(a0p, w1, cc[0][1]); cc[1][1] = fma2(a1p, w1, cc[1][1]);
            cc[2][1] = fma2(a2p, w1, cc[2][1]); cc[3][1] = fma2(a3p, w1, cc[3][1]);
            cc[0][2] = fma2(a0p, w2, cc[0][2]); cc[1][2] = fma2(a1p, w2, cc[1][2]);
            cc[2][2] = fma2(a2p, w2, cc[2][2]); cc[3][2] = fma2(a3p, w2, cc[3][2]);
            cc[0][3] = fma2(a0p, w3, cc[0][3]); cc[1][3] = fma2(a1p, w3, cc[1][3]);
            cc[2][3] = fma2(a2p, w3, cc[2][3]); cc[3][3] = fma2(a3p, w3, cc[3][3]);
        }
        __syncthreads();
    }

    // epilogue: m = p*32 + tx*2 (+1): s = s0 + (p>>1), b = (p&1)*32 + tx*2
    #pragma unroll
    for (int jn = 0; jn < 4; jn++) {
        int g = g0 + ty * 4 + jn;
        float bsum = bih[g] + bhh[g];
        #pragma unroll
        for (int p = 0; p < 4; p++) {
            float2 v = unpack2(cc[p][jn]);
            int s = s0 + (p >> 1);
            int b = (p & 1) * 32 + tx * 2;
            *(float2*)&g_xg[(size_t)s * (GG * BB) + (size_t)g * BB + b] =
                make_float2(v.x + bsum, v.y + bsum);
        }
    }
}

// ---------------------------------------------------------------------------
// Release/acquire grid barrier (monotonic; graph-replay safe). grid = 128.
// ---------------------------------------------------------------------------
__device__ __forceinline__ void grid_sync128() {
    __syncthreads();
    if (threadIdx.x == 0) {
        unsigned t;
        asm volatile("atom.release.gpu.global.add.u32 %0, [%1], 1;"
                     : "=r"(t) : "l"(&g_bar) : "memory");
        unsigned target = (t / 128u + 1u) * 128u;
        unsigned cur;
        do {
            asm volatile("ld.acquire.gpu.global.u32 %0, [%1];"
                         : "=r"(cur) : "l"(&g_bar) : "memory");
        } while (cur < target);
    }
    __syncthreads();
}

// ---------------------------------------------------------------------------
// Phase B: persistent LSTM recurrence. 128 CTAs x 256 threads (8 warps).
// CTA owns 4 h-columns j0..j0+3 (8 f32x2 streams). Warp wi owns k-range
// [wi*64, wi*64+64) x ALL 64 b (lane, lane+32): W amortized over 64 b
// (4B LDS per FFMA2). h read directly from L2 via __ldcg into registers,
// double-buffered in 16-k chunks -- no SMEM staging, no cp.async.
// SMEM: W pairs 32KB | scratch 32KB = 64KB.
// ---------------------------------------------------------------------------
__global__ void __launch_bounds__(256, 1) lstm_kernel(
    const float* __restrict__ Whh, float* __restrict__ out, int write_c)
{
    extern __shared__ float smf[];
    float*  Ws  = smf;                      // (st*512+k)*2 : {w_jA, w_jB}
    float2* scp = (float2*)(smf + 8192);    // [st8][bh2][kr8][lane32]

    const int tid  = threadIdx.x;
    const int wi   = tid >> 5;              // warp = k-range index (0..7)
    const int lane = tid & 31;
    const int j0   = blockIdx.x * 4;
    const int kbase = wi * 64;

    // W pairs: st = g*2+jp covers rows (g*H + j0+2jp, +1)
    #pragma unroll
    for (int st = 0; st < 8; st++) {
        int g = st >> 1, jp = st & 1;
        const float* r0 = Whh + (size_t)(g * HH + j0 + 2 * jp) * HH;
        const float* r1 = r0 + HH;
        #pragma unroll
        for (int i = 0; i < 2; i++) {
            int k = tid + i * 256;
            *(float2*)&Ws[(st * 512 + k) * 2] = make_float2(r0[k], r1[k]);
        }
    }

    // zero h read-buffer for step 0
    g_h[1][(j0 + (tid >> 6)) * 64 + (tid & 63)] = 0.f;

    const int b  = tid & 63;        // epilogue: one (b, j) per thread
    const int jj = tid >> 6;
    const int j  = j0 + jj;
    const int jp_r  = jj >> 1;
    const int comp  = jj & 1;
    const int bh_r  = b >> 5;
    const int lane_r = b & 31;

    float c_reg = 0.f, h_val = 0.f;

    #pragma unroll 1
    for (int s = 0; s < SS; s++) {
        grid_sync128();

        // prefetch xg (latency hides under GEMM)
        float xgv[4];
        const float* xgs = g_xg + (size_t)s * (GG * BB);
        #pragma unroll
        for (int g = 0; g < 4; g++)
            xgv[g] = __ldg(&xgs[(g * HH + j) * BB + b]);

        const float* hsrc = g_h[(s + 1) & 1];

        u64 acc[8][2];
        #pragma unroll
        for (int st = 0; st < 8; st++) { acc[st][0] = 0ull; acc[st][1] = 0ull; }

        float hreg[2][32];
        // prefetch chunk 0: 16 k x {lane, lane+32}
        #pragma unroll
        for (int i = 0; i < 16; i++) {
            hreg[0][i]      = __ldcg(&hsrc[(kbase + i) * 64 + lane]);
            hreg[0][16 + i] = __ldcg(&hsrc[(kbase + i) * 64 + 32 + lane]);
        }

        #pragma unroll
        for (int c = 0; c < 4; c++) {
            const int cur = c & 1, nxt = cur ^ 1;
            if (c < 3) {
                const int kn = kbase + (c + 1) * 16;
                #pragma unroll
                for (int i = 0; i < 16; i++) {
                    hreg[nxt][i]      = __ldcg(&hsrc[(kn + i) * 64 + lane]);
                    hreg[nxt][16 + i] = __ldcg(&hsrc[(kn + i) * 64 + 32 + lane]);
                }
            }
            const int kg0 = kbase + c * 16;
            #pragma unroll
            for (int kk = 0; kk < 16; kk += 2) {
                const int kg = kg0 + kk;
                u64 dA0 = pack2(hreg[cur][kk],      hreg[cur][kk]);
                u64 dB0 = pack2(hreg[cur][16 + kk], hreg[cur][16 + kk]);
                u64 dA1 = pack2(hreg[cur][kk + 1],      hreg[cur][kk + 1]);
                u64 dB1 = pack2(hreg[cur][16 + kk + 1], hreg[cur][16 + kk + 1]);
                #pragma unroll
                for (int st = 0; st < 8; st++) {
                    ulonglong2 wv = *(const ulonglong2*)&Ws[(st * 512 + kg) * 2];
                    acc[st][0] = fma2(dA0, wv.x, acc[st][0]);
                    acc[st][1] = fma2(dB0, wv.x, acc[st][1]);
                    acc[st][0] = fma2(dA1, wv.y, acc[st][0]);
                    acc[st][1] = fma2(dB1, wv.y, acc[st][1]);
                }
            }
        }

        // partials -> scratch: [st][bh][kr][lane]
        #pragma unroll
        for (int st = 0; st < 8; st++) {
            scp[((st * 2 + 0) * 8 + wi) * 32 + lane] = *(float2*)&acc[st][0];
            scp[((st * 2 + 1) * 8 + wi) * 32 + lane] = *(float2*)&acc[st][1];
        }
        __syncthreads();

        // cross-warp reduce (8 k-range partials) + gates
        float gt[4];
        #pragma unroll
        for (int g = 0; g < 4; g++) {
            int st = g * 2 + jp_r;
            const float2* base = &scp[((st * 2 + bh_r) * 8) * 32 + lane_r];
            float sx = 0.f, sy = 0.f;
            #pragma unroll
            for (int kr = 0; kr < 8; kr++) {
                float2 p = base[kr * 32];
                sx += p.x; sy += p.y;
            }
            gt[g] = (comp ? sy : sx) + xgv[g];
        }
        float ig = sigf(gt[0]), fg = sigf(gt[1]);
        float gg = tanh_f(gt[2]), og = sigf(gt[3]);
        c_reg = fg * c_reg + ig * gg;
        h_val = og * tanh_f(c_reg);

        g_h[s & 1][j * 64 + b] = h_val;
    }

    out[b * HH + j] = h_val;
    if (write_c) out[BB * HH + b * HH + j] = c_reg;
}

// ---------------------------------------------------------------------------
// kernel_launch  (2 launches -> ncu -s 5 lands on a real kernel)
// ---------------------------------------------------------------------------
extern "C" void kernel_launch(void* const* d_in, const int* in_sizes, int n_in,
                              void* d_out, int out_size)
{
    const void*  seq = d_in[0];
    const float* emb = (const float*)d_in[1];
    const float* Wih = (const float*)d_in[2];
    const float* Whh = (const float*)d_in[3];
    const float* bih = (const float*)d_in[4];
    const float* bhh = (const float*)d_in[5];
    float* out = (float*)d_out;

    (void)in_sizes; (void)n_in;
    int write_c = (out_size >= 2 * BB * HH) ? 1 : 0;

    // 64 KB dynamic SMEM: W pairs 32K + scratch 32K
    static const int kSmem = (8192 + 8192) * (int)sizeof(float);
    cudaFuncSetAttribute(lstm_kernel, cudaFuncAttributeMaxDynamicSharedMemorySize, kSmem);

    xgates_gemm<<<dim3(GG / 64, SS / 2), 256>>>(seq, emb, Wih, bih, bhh);
    lstm_kernel<<<HH / 4, 256, kSmem>>>(Whh, out, write_c);
}